// round 2
// baseline (speedup 1.0000x reference)
#include <cuda_runtime.h>
#include <cstdint>

#define N_ATOMS    1000000
#define DIM        128
#define NUM_GRAPHS 100000
#define TILE_M     128
#define LDA        136   /* DIM + 8 pad: conflict-free A and B smem reads */
#define NTHREADS   256

// pooled scratch [NUM_GRAPHS, DIM] — device global (no allocs allowed)
__device__ float g_pooled[(size_t)NUM_GRAPHS * DIM];

__device__ __forceinline__ uint32_t f2tf(float x) {
    uint32_t r;
    asm("cvt.rna.tf32.f32 %0, %1;" : "=r"(r) : "f"(x));
    return r;
}

__device__ __forceinline__ float silu_f(float x) {
    return x / (1.0f + __expf(-x));
}

__device__ __forceinline__ void mma_tf32(float& c0, float& c1, float& c2, float& c3,
                                         uint32_t a0, uint32_t a1, uint32_t a2, uint32_t a3,
                                         uint32_t b0, uint32_t b1)
{
    asm volatile(
        "mma.sync.aligned.m16n8k8.row.col.f32.tf32.tf32.f32 "
        "{%0,%1,%2,%3}, {%4,%5,%6,%7}, {%8,%9}, {%0,%1,%2,%3};\n"
        : "+f"(c0), "+f"(c1), "+f"(c2), "+f"(c3)
        : "r"(a0), "r"(a1), "r"(a2), "r"(a3), "r"(b0), "r"(b1));
}

// C[128,128] += A[128,128] * B[128,128]; A row-major in sA (ld=LDA),
// B row-major (k, n) in sW (ld=LDA). 8 warps: warp_m in 0..3 (32 rows),
// warp_n in 0..1 (64 cols). acc[mi][ni][4] per warp.
__device__ __forceinline__ void gemm128(const float* __restrict__ sA,
                                        const float* __restrict__ sW,
                                        float (&acc)[2][8][4],
                                        int warp_m, int warp_n, int g, int t)
{
    #pragma unroll
    for (int k0 = 0; k0 < DIM; k0 += 8) {
        uint32_t a[2][4];
        #pragma unroll
        for (int mi = 0; mi < 2; mi++) {
            const float* ap = sA + (warp_m * 32 + mi * 16) * LDA + k0;
            a[mi][0] = f2tf(ap[g * LDA + t]);
            a[mi][1] = f2tf(ap[(g + 8) * LDA + t]);
            a[mi][2] = f2tf(ap[g * LDA + t + 4]);
            a[mi][3] = f2tf(ap[(g + 8) * LDA + t + 4]);
        }
        #pragma unroll
        for (int ni = 0; ni < 8; ni++) {
            const float* bp = sW + (k0 + t) * LDA + warp_n * 64 + ni * 8 + g;
            uint32_t b0 = f2tf(bp[0]);
            uint32_t b1 = f2tf(bp[4 * LDA]);
            #pragma unroll
            for (int mi = 0; mi < 2; mi++)
                mma_tf32(acc[mi][ni][0], acc[mi][ni][1], acc[mi][ni][2], acc[mi][ni][3],
                         a[mi][0], a[mi][1], a[mi][2], a[mi][3], b0, b1);
        }
    }
}

// ---------------------------------------------------------------------------
// Kernel 0: zero the pooled scratch (must be re-done every graph replay)
// ---------------------------------------------------------------------------
__global__ void zero_pooled_kernel()
{
    size_t idx = (size_t)blockIdx.x * blockDim.x + threadIdx.x;
    size_t n4  = (size_t)NUM_GRAPHS * DIM / 4;
    float4* p  = reinterpret_cast<float4*>(g_pooled);
    for (size_t i = idx; i < n4; i += (size_t)gridDim.x * blockDim.x)
        p[i] = make_float4(0.f, 0.f, 0.f, 0.f);
}

// ---------------------------------------------------------------------------
// Kernel 1: per-atom MLP + feat passthrough + segment-sum pooling
// batch is int32 (JAX x64 disabled: astype(int64) is a silent no-op to int32)
// ---------------------------------------------------------------------------
__global__ void __launch_bounds__(NTHREADS, 1) atom_mlp_pool_kernel(
    const float* __restrict__ feat,
    const int* __restrict__ batch,
    const float* __restrict__ W1, const float* __restrict__ b1,
    const float* __restrict__ W2, const float* __restrict__ b2,
    float* __restrict__ out_feat /* may be null if out buffer too small */)
{
    extern __shared__ float smem[];
    float* sA = smem;                         // [TILE_M][LDA]  X tile, then H1
    float* sW = smem + TILE_M * LDA;          // [DIM][LDA]     W1, then W2, then H2
    int*   sB = (int*)(smem + 2 * TILE_M * LDA);   // [TILE_M]  batch ids

    const int tid   = threadIdx.x;
    const int tile0 = blockIdx.x * TILE_M;

    // ---- load X tile into smem + write feat passthrough from same data ----
    #pragma unroll
    for (int it = 0; it < (TILE_M * DIM / 4) / NTHREADS; ++it) {
        int i   = tid + it * NTHREADS;
        int r   = i >> 5;          // 32 float4 per row
        int c4  = i & 31;
        int row = tile0 + r;
        float4 v = make_float4(0.f, 0.f, 0.f, 0.f);
        if (row < N_ATOMS)
            v = reinterpret_cast<const float4*>(feat)[(size_t)row * 32 + c4];
        *reinterpret_cast<float4*>(sA + r * LDA + c4 * 4) = v;
        if (out_feat != nullptr && row < N_ATOMS)
            reinterpret_cast<float4*>(out_feat)[(size_t)row * 32 + c4] = v;
    }
    if (tid < TILE_M) {
        int row = tile0 + tid;
        sB[tid] = (row < N_ATOMS) ? batch[row] : -1;
    }
    // ---- load W1 ----
    #pragma unroll
    for (int it = 0; it < (DIM * DIM / 4) / NTHREADS; ++it) {
        int i  = tid + it * NTHREADS;
        int k  = i >> 5;
        int c4 = i & 31;
        float4 v = reinterpret_cast<const float4*>(W1)[i];
        *reinterpret_cast<float4*>(sW + k * LDA + c4 * 4) = v;
    }
    __syncthreads();

    const int lane   = tid & 31;
    const int wid    = tid >> 5;
    const int warp_m = wid & 3;
    const int warp_n = wid >> 2;
    const int g      = lane >> 2;
    const int t      = lane & 3;

    float acc[2][8][4];
    #pragma unroll
    for (int mi = 0; mi < 2; mi++)
        #pragma unroll
        for (int ni = 0; ni < 8; ni++)
            #pragma unroll
            for (int q = 0; q < 4; q++) acc[mi][ni][q] = 0.f;

    // ---- GEMM1: H1 = X @ W1 ----
    gemm128(sA, sW, acc, warp_m, warp_n, g, t);
    __syncthreads();   // all warps done reading sA/sW

    // ---- epilogue1: H1 = silu(acc + b1) -> sA; load W2 -> sW ----
    #pragma unroll
    for (int ni = 0; ni < 8; ni++) {
        int col = warp_n * 64 + ni * 8 + 2 * t;
        float bb0 = b1[col], bb1 = b1[col + 1];
        #pragma unroll
        for (int mi = 0; mi < 2; mi++) {
            int r0 = warp_m * 32 + mi * 16 + g;
            sA[r0 * LDA + col]           = silu_f(acc[mi][ni][0] + bb0);
            sA[r0 * LDA + col + 1]       = silu_f(acc[mi][ni][1] + bb1);
            sA[(r0 + 8) * LDA + col]     = silu_f(acc[mi][ni][2] + bb0);
            sA[(r0 + 8) * LDA + col + 1] = silu_f(acc[mi][ni][3] + bb1);
        }
    }
    #pragma unroll
    for (int it = 0; it < (DIM * DIM / 4) / NTHREADS; ++it) {
        int i  = tid + it * NTHREADS;
        int k  = i >> 5;
        int c4 = i & 31;
        float4 v = reinterpret_cast<const float4*>(W2)[i];
        *reinterpret_cast<float4*>(sW + k * LDA + c4 * 4) = v;
    }
    __syncthreads();

    #pragma unroll
    for (int mi = 0; mi < 2; mi++)
        #pragma unroll
        for (int ni = 0; ni < 8; ni++)
            #pragma unroll
            for (int q = 0; q < 4; q++) acc[mi][ni][q] = 0.f;

    // ---- GEMM2: H2 = H1 @ W2 ----
    gemm128(sA, sW, acc, warp_m, warp_n, g, t);
    __syncthreads();   // all warps done reading sW

    // ---- epilogue2: H2 = acc + b2 -> sW (reuse as H buffer) ----
    float* sH = sW;
    #pragma unroll
    for (int ni = 0; ni < 8; ni++) {
        int col = warp_n * 64 + ni * 8 + 2 * t;
        float bb0 = b2[col], bb1 = b2[col + 1];
        #pragma unroll
        for (int mi = 0; mi < 2; mi++) {
            int r0 = warp_m * 32 + mi * 16 + g;
            sH[r0 * LDA + col]           = acc[mi][ni][0] + bb0;
            sH[r0 * LDA + col + 1]       = acc[mi][ni][1] + bb1;
            sH[(r0 + 8) * LDA + col]     = acc[mi][ni][2] + bb0;
            sH[(r0 + 8) * LDA + col + 1] = acc[mi][ni][3] + bb1;
        }
    }
    __syncthreads();

    // ---- segment-sum pooling: batch is sorted => run-length reduce per
    // column, one atomicAdd per (run, column). Threads 0..127: cols, rows
    // 0..63. Threads 128..255: same cols, rows 64..127.
    {
        int col  = tid & 127;
        int rbeg = (tid >> 7) * 64;
        int rend = rbeg + 64;
        float s  = 0.f;
        int  cur = sB[rbeg];
        for (int r = rbeg; r < rend; ++r) {
            int bi = sB[r];
            if (bi != cur) {
                if (cur >= 0 && cur < NUM_GRAPHS)
                    atomicAdd(&g_pooled[(size_t)cur * DIM + col], s);
                s = 0.f;
                cur = bi;
            }
            s += sH[r * LDA + col];
        }
        if (cur >= 0 && cur < NUM_GRAPHS)
            atomicAdd(&g_pooled[(size_t)cur * DIM + col], s);
    }
}

// ---------------------------------------------------------------------------
// Kernel 2: graph head  out[g] = silu(pooled[g] @ W3 + b3) @ W4 + b4
// ---------------------------------------------------------------------------
__global__ void __launch_bounds__(NTHREADS, 1) graph_head_kernel(
    const float* __restrict__ W3, const float* __restrict__ b3,
    const float* __restrict__ W4, const float* __restrict__ b4,
    float* __restrict__ out_head)
{
    extern __shared__ float smem[];
    float* sA    = smem;                        // pooled tile [128][LDA]
    float* sW    = smem + TILE_M * LDA;         // W3 [128][LDA]
    float* sPart = smem + 2 * TILE_M * LDA;     // [2][128] partial dot per warp_n
    float* sW4   = sPart + 2 * TILE_M;          // [128]

    const int tid   = threadIdx.x;
    const int tile0 = blockIdx.x * TILE_M;

    #pragma unroll
    for (int it = 0; it < (TILE_M * DIM / 4) / NTHREADS; ++it) {
        int i   = tid + it * NTHREADS;
        int r   = i >> 5;
        int c4  = i & 31;
        int row = tile0 + r;
        float4 v = make_float4(0.f, 0.f, 0.f, 0.f);
        if (row < NUM_GRAPHS)
            v = reinterpret_cast<const float4*>(g_pooled)[(size_t)row * 32 + c4];
        *reinterpret_cast<float4*>(sA + r * LDA + c4 * 4) = v;
    }
    #pragma unroll
    for (int it = 0; it < (DIM * DIM / 4) / NTHREADS; ++it) {
        int i  = tid + it * NTHREADS;
        int k  = i >> 5;
        int c4 = i & 31;
        float4 v = reinterpret_cast<const float4*>(W3)[i];
        *reinterpret_cast<float4*>(sW + k * LDA + c4 * 4) = v;
    }
    if (tid < DIM) sW4[tid] = W4[tid];
    __syncthreads();

    const int lane   = tid & 31;
    const int wid    = tid >> 5;
    const int warp_m = wid & 3;
    const int warp_n = wid >> 2;
    const int g      = lane >> 2;
    const int t      = lane & 3;

    float acc[2][8][4];
    #pragma unroll
    for (int mi = 0; mi < 2; mi++)
        #pragma unroll
        for (int ni = 0; ni < 8; ni++)
            #pragma unroll
            for (int q = 0; q < 4; q++) acc[mi][ni][q] = 0.f;

    gemm128(sA, sW, acc, warp_m, warp_n, g, t);

    // fused: silu(acc + b3) dotted with W4 -> per-row partials
    float p[2][2] = {{0.f, 0.f}, {0.f, 0.f}};   // [mi][row-half(g / g+8)]
    #pragma unroll
    for (int ni = 0; ni < 8; ni++) {
        int col = warp_n * 64 + ni * 8 + 2 * t;
        float bb0 = b3[col], bb1 = b3[col + 1];
        float w40 = sW4[col], w41 = sW4[col + 1];
        #pragma unroll
        for (int mi = 0; mi < 2; mi++) {
            p[mi][0] += silu_f(acc[mi][ni][0] + bb0) * w40
                      + silu_f(acc[mi][ni][1] + bb1) * w41;
            p[mi][1] += silu_f(acc[mi][ni][2] + bb0) * w40
                      + silu_f(acc[mi][ni][3] + bb1) * w41;
        }
    }
    // reduce over t (lanes 4g+0..3 share the same rows)
    #pragma unroll
    for (int mi = 0; mi < 2; mi++)
        #pragma unroll
        for (int h = 0; h < 2; h++) {
            p[mi][h] += __shfl_xor_sync(0xffffffffu, p[mi][h], 1);
            p[mi][h] += __shfl_xor_sync(0xffffffffu, p[mi][h], 2);
        }
    if (t == 0) {
        int base = warp_n * TILE_M + warp_m * 32 + g;
        sPart[base]      = p[0][0];
        sPart[base + 8]  = p[0][1];
        sPart[base + 16] = p[1][0];
        sPart[base + 24] = p[1][1];
    }
    __syncthreads();

    if (tid < TILE_M) {
        int row = tile0 + tid;
        if (row < NUM_GRAPHS)
            out_head[row] = sPart[tid] + sPart[TILE_M + tid] + b4[0];
    }
}

// ---------------------------------------------------------------------------
// launcher
// ---------------------------------------------------------------------------
extern "C" void kernel_launch(void* const* d_in, const int* in_sizes, int n_in,
                              void* d_out, int out_size)
{
    const float* feat  = (const float*)d_in[0];
    const int*   batch = (const int*)d_in[1];   // int32 (JAX x64 disabled)
    const float* W1    = (const float*)d_in[2];
    const float* b1    = (const float*)d_in[3];
    const float* W2    = (const float*)d_in[4];
    const float* b2    = (const float*)d_in[5];
    const float* W3    = (const float*)d_in[6];
    const float* b3    = (const float*)d_in[7];
    const float* W4    = (const float*)d_in[8];
    const float* b4    = (const float*)d_in[9];

    float* out      = (float*)d_out;
    float* out_head = out;                 // [NUM_GRAPHS * 1], first tuple elem
    // feat passthrough only if the harness allocated room for both outputs
    float* out_feat = nullptr;
    const long long need = (long long)NUM_GRAPHS + (long long)N_ATOMS * DIM;
    if ((long long)out_size >= need)
        out_feat = out + NUM_GRAPHS;       // [N_ATOMS * DIM]

    const int smem_atom = (2 * TILE_M * LDA) * 4 + TILE_M * 4;            // ~139.8 KB
    const int smem_head = (2 * TILE_M * LDA + 2 * TILE_M + DIM) * 4;      // ~140.8 KB

    static int attr_done = 0;
    if (!attr_done) {
        cudaFuncSetAttribute(atom_mlp_pool_kernel,
                             cudaFuncAttributeMaxDynamicSharedMemorySize, smem_atom);
        cudaFuncSetAttribute(graph_head_kernel,
                             cudaFuncAttributeMaxDynamicSharedMemorySize, smem_head);
        attr_done = 1;
    }

    zero_pooled_kernel<<<2048, 256>>>();

    int atom_blocks = (N_ATOMS + TILE_M - 1) / TILE_M;       // 7813
    atom_mlp_pool_kernel<<<atom_blocks, NTHREADS, smem_atom>>>(
        feat, batch, W1, b1, W2, b2, out_feat);

    int head_blocks = (NUM_GRAPHS + TILE_M - 1) / TILE_M;    // 782
    graph_head_kernel<<<head_blocks, NTHREADS, smem_head>>>(
        W3, b3, W4, b4, out_head);
}

// round 3
// speedup vs baseline: 1.2510x; 1.2510x over previous
#include <cuda_runtime.h>
#include <cstdint>

#define N_ATOMS    1000000
#define DIM        128
#define NUM_GRAPHS 100000
#define TILE_M     256        /* atom rows per block */
#define LDA        136        /* DIM + 8 pad */
#define NTHREADS   512        /* 16 warps: 8 m-warps x 2 n-warps */

// pooled scratch [NUM_GRAPHS, DIM] — device global (no allocs allowed)
__device__ float g_pooled[(size_t)NUM_GRAPHS * DIM];

__device__ __forceinline__ float f2tf_f(float x) {
    uint32_t r;
    asm("cvt.rna.tf32.f32 %0, %1;" : "=r"(r) : "f"(x));
    return __uint_as_float(r);
}

__device__ __forceinline__ float silu_f(float x) {
    return x / (1.0f + __expf(-x));
}

__device__ __forceinline__ void mma_tf32(float& c0, float& c1, float& c2, float& c3,
                                         uint32_t a0, uint32_t a1, uint32_t a2, uint32_t a3,
                                         uint32_t b0, uint32_t b1)
{
    asm volatile(
        "mma.sync.aligned.m16n8k8.row.col.f32.tf32.tf32.f32 "
        "{%0,%1,%2,%3}, {%4,%5,%6,%7}, {%8,%9}, {%0,%1,%2,%3};\n"
        : "+f"(c0), "+f"(c1), "+f"(c2), "+f"(c3)
        : "r"(a0), "r"(a1), "r"(a2), "r"(a3), "r"(b0), "r"(b1));
}

// C[rows x 128] += A(rows x 128, tf32-pre-rounded, ld=LDA) * B(128x128 row-major
// [k][n], tf32-pre-rounded, ld=LDA). Warp handles 32 rows (warp_m) x 64 cols
// (warp_n). Data already tf32-rounded: raw bit loads, no cvt in the hot loop.
__device__ __forceinline__ void gemm_tile(const uint32_t* __restrict__ sA,
                                          const uint32_t* __restrict__ sW,
                                          float (&acc)[2][8][4],
                                          int warp_m, int warp_n, int g, int t)
{
    #pragma unroll
    for (int k0 = 0; k0 < DIM; k0 += 8) {
        uint32_t a[2][4];
        #pragma unroll
        for (int mi = 0; mi < 2; mi++) {
            const uint32_t* ap = sA + (warp_m * 32 + mi * 16) * LDA + k0;
            a[mi][0] = ap[g * LDA + t];
            a[mi][1] = ap[(g + 8) * LDA + t];
            a[mi][2] = ap[g * LDA + t + 4];
            a[mi][3] = ap[(g + 8) * LDA + t + 4];
        }
        #pragma unroll
        for (int ni = 0; ni < 8; ni++) {
            const uint32_t* bp = sW + (k0 + t) * LDA + warp_n * 64 + ni * 8 + g;
            uint32_t b0 = bp[0];
            uint32_t b1 = bp[4 * LDA];
            #pragma unroll
            for (int mi = 0; mi < 2; mi++)
                mma_tf32(acc[mi][ni][0], acc[mi][ni][1], acc[mi][ni][2], acc[mi][ni][3],
                         a[mi][0], a[mi][1], a[mi][2], a[mi][3], b0, b1);
        }
    }
}

// ---------------------------------------------------------------------------
// Kernel 0: zero the pooled scratch (re-done every graph replay)
// ---------------------------------------------------------------------------
__global__ void zero_pooled_kernel()
{
    size_t idx = (size_t)blockIdx.x * blockDim.x + threadIdx.x;
    size_t n4  = (size_t)NUM_GRAPHS * DIM / 4;
    float4* p  = reinterpret_cast<float4*>(g_pooled);
    for (size_t i = idx; i < n4; i += (size_t)gridDim.x * blockDim.x)
        p[i] = make_float4(0.f, 0.f, 0.f, 0.f);
}

// ---------------------------------------------------------------------------
// Kernel 1: per-atom MLP + feat passthrough + segment-sum pooling
// batch is int32 (JAX x64 disabled)
// ---------------------------------------------------------------------------
__global__ void __launch_bounds__(NTHREADS, 1) atom_mlp_pool_kernel(
    const float* __restrict__ feat,
    const int* __restrict__ batch,
    const float* __restrict__ W1, const float* __restrict__ b1,
    const float* __restrict__ W2, const float* __restrict__ b2,
    float* __restrict__ out_feat)
{
    extern __shared__ float smem[];
    float* sA = smem;                              // [TILE_M][LDA] X -> H1
    float* sW = smem + TILE_M * LDA;               // [DIM][LDA]    W1 -> W2 -> H2
    int*   sB = (int*)(smem + TILE_M * LDA + DIM * LDA);  // [TILE_M] batch ids

    const int tid   = threadIdx.x;
    const int tile0 = blockIdx.x * TILE_M;

    // ---- load X tile (tf32-rounded) + exact feat passthrough ----
    #pragma unroll
    for (int it = 0; it < (TILE_M * DIM / 4) / NTHREADS; ++it) {
        int i   = tid + it * NTHREADS;
        int r   = i >> 5;             // 32 float4 per row
        int c4  = i & 31;
        int row = tile0 + r;
        float4 v = make_float4(0.f, 0.f, 0.f, 0.f);
        if (row < N_ATOMS)
            v = reinterpret_cast<const float4*>(feat)[(size_t)row * 32 + c4];
        if (out_feat != nullptr && row < N_ATOMS)
            reinterpret_cast<float4*>(out_feat)[(size_t)row * 32 + c4] = v;
        float4 w = make_float4(f2tf_f(v.x), f2tf_f(v.y), f2tf_f(v.z), f2tf_f(v.w));
        *reinterpret_cast<float4*>(sA + r * LDA + c4 * 4) = w;
    }
    if (tid < TILE_M) {
        int row = tile0 + tid;
        sB[tid] = (row < N_ATOMS) ? batch[row] : -1;
    }
    // ---- load W1 (tf32-rounded) ----
    #pragma unroll
    for (int it = 0; it < (DIM * DIM / 4) / NTHREADS; ++it) {
        int i  = tid + it * NTHREADS;
        int k  = i >> 5;
        int c4 = i & 31;
        float4 v = reinterpret_cast<const float4*>(W1)[i];
        float4 w = make_float4(f2tf_f(v.x), f2tf_f(v.y), f2tf_f(v.z), f2tf_f(v.w));
        *reinterpret_cast<float4*>(sW + k * LDA + c4 * 4) = w;
    }
    __syncthreads();

    const int lane   = tid & 31;
    const int wid    = tid >> 5;
    const int warp_m = wid & 7;      // 8 m-warps x 32 rows = 256
    const int warp_n = wid >> 3;     // 2 n-warps x 64 cols
    const int g      = lane >> 2;
    const int t      = lane & 3;

    float acc[2][8][4];
    #pragma unroll
    for (int mi = 0; mi < 2; mi++)
        #pragma unroll
        for (int ni = 0; ni < 8; ni++)
            #pragma unroll
            for (int q = 0; q < 4; q++) acc[mi][ni][q] = 0.f;

    // ---- GEMM1: H1 = X @ W1 ----
    gemm_tile((const uint32_t*)sA, (const uint32_t*)sW, acc, warp_m, warp_n, g, t);
    __syncthreads();

    // ---- epilogue1: H1 = tf32(silu(acc + b1)) -> sA; load W2 -> sW ----
    #pragma unroll
    for (int ni = 0; ni < 8; ni++) {
        int col = warp_n * 64 + ni * 8 + 2 * t;
        float bb0 = b1[col], bb1 = b1[col + 1];
        #pragma unroll
        for (int mi = 0; mi < 2; mi++) {
            int r0 = warp_m * 32 + mi * 16 + g;
            sA[r0 * LDA + col]           = f2tf_f(silu_f(acc[mi][ni][0] + bb0));
            sA[r0 * LDA + col + 1]       = f2tf_f(silu_f(acc[mi][ni][1] + bb1));
            sA[(r0 + 8) * LDA + col]     = f2tf_f(silu_f(acc[mi][ni][2] + bb0));
            sA[(r0 + 8) * LDA + col + 1] = f2tf_f(silu_f(acc[mi][ni][3] + bb1));
        }
    }
    #pragma unroll
    for (int it = 0; it < (DIM * DIM / 4) / NTHREADS; ++it) {
        int i  = tid + it * NTHREADS;
        int k  = i >> 5;
        int c4 = i & 31;
        float4 v = reinterpret_cast<const float4*>(W2)[i];
        float4 w = make_float4(f2tf_f(v.x), f2tf_f(v.y), f2tf_f(v.z), f2tf_f(v.w));
        *reinterpret_cast<float4*>(sW + k * LDA + c4 * 4) = w;
    }
    __syncthreads();

    #pragma unroll
    for (int mi = 0; mi < 2; mi++)
        #pragma unroll
        for (int ni = 0; ni < 8; ni++)
            #pragma unroll
            for (int q = 0; q < 4; q++) acc[mi][ni][q] = 0.f;

    // ---- GEMM2: H2 = H1 @ W2 ----
    gemm_tile((const uint32_t*)sA, (const uint32_t*)sW, acc, warp_m, warp_n, g, t);
    __syncthreads();

    // ---- epilogue2: H2 = acc + b2 -> sW (reuse as H buffer) ----
    float* sH = sW;
    #pragma unroll
    for (int ni = 0; ni < 8; ni++) {
        int col = warp_n * 64 + ni * 8 + 2 * t;
        float bb0 = b2[col], bb1 = b2[col + 1];
        #pragma unroll
        for (int mi = 0; mi < 2; mi++) {
            int r0 = warp_m * 32 + mi * 16 + g;
            // NOTE: sH is [DIM][LDA] sized for 128 rows only -> must map 256
            // H2 rows. Use sA for upper half instead (X no longer needed).
            float* dst = (r0 < 128) ? sH : (sA - 128 * LDA);
            dst[r0 * LDA + col]           = acc[mi][ni][0] + bb0;
            dst[r0 * LDA + col + 1]       = acc[mi][ni][1] + bb1;
            dst[(r0 + 8) * LDA + col]     = acc[mi][ni][2] + bb0;
            dst[(r0 + 8) * LDA + col + 1] = acc[mi][ni][3] + bb1;
        }
    }
    __syncthreads();

    // ---- segment-sum pooling (batch sorted => run-length per column) ----
    // rows 0..127 of H2 live in sW, rows 128..255 live in sA[0..127].
    {
        int col   = tid & 127;
        int chunk = tid >> 7;              // 0..3, 64 rows each
        int rbeg  = chunk * 64;
        float s   = 0.f;
        int  cur  = sB[rbeg];
        for (int r = rbeg; r < rbeg + 64; ++r) {
            int bi = sB[r];
            if (bi != cur) {
                if (cur >= 0 && cur < NUM_GRAPHS)
                    atomicAdd(&g_pooled[(size_t)cur * DIM + col], s);
                s = 0.f;
                cur = bi;
            }
            const float* src = (r < 128) ? sH : (sA - 128 * LDA);
            s += src[r * LDA + col];
        }
        if (cur >= 0 && cur < NUM_GRAPHS)
            atomicAdd(&g_pooled[(size_t)cur * DIM + col], s);
    }
}

// ---------------------------------------------------------------------------
// Kernel 2: graph head  out[g] = silu(pooled[g] @ W3 + b3) @ W4 + b4
// 128-row tiles, 256 threads (8 warps)
// ---------------------------------------------------------------------------
#define HT 128
#define HNT 256
__global__ void __launch_bounds__(HNT, 1) graph_head_kernel(
    const float* __restrict__ W3, const float* __restrict__ b3,
    const float* __restrict__ W4, const float* __restrict__ b4,
    float* __restrict__ out_head)
{
    extern __shared__ float smem[];
    float* sA    = smem;                        // pooled tile [128][LDA]
    float* sW    = smem + HT * LDA;             // W3 [128][LDA]
    float* sPart = smem + 2 * HT * LDA;         // [2][128]
    float* sW4   = sPart + 2 * HT;              // [128]

    const int tid   = threadIdx.x;
    const int tile0 = blockIdx.x * HT;

    #pragma unroll
    for (int it = 0; it < (HT * DIM / 4) / HNT; ++it) {
        int i   = tid + it * HNT;
        int r   = i >> 5;
        int c4  = i & 31;
        int row = tile0 + r;
        float4 v = make_float4(0.f, 0.f, 0.f, 0.f);
        if (row < NUM_GRAPHS)
            v = reinterpret_cast<const float4*>(g_pooled)[(size_t)row * 32 + c4];
        float4 w = make_float4(f2tf_f(v.x), f2tf_f(v.y), f2tf_f(v.z), f2tf_f(v.w));
        *reinterpret_cast<float4*>(sA + r * LDA + c4 * 4) = w;
    }
    #pragma unroll
    for (int it = 0; it < (DIM * DIM / 4) / HNT; ++it) {
        int i  = tid + it * HNT;
        int k  = i >> 5;
        int c4 = i & 31;
        float4 v = reinterpret_cast<const float4*>(W3)[i];
        float4 w = make_float4(f2tf_f(v.x), f2tf_f(v.y), f2tf_f(v.z), f2tf_f(v.w));
        *reinterpret_cast<float4*>(sW + k * LDA + c4 * 4) = w;
    }
    if (tid < DIM) sW4[tid] = W4[tid];
    __syncthreads();

    const int lane   = tid & 31;
    const int wid    = tid >> 5;
    const int warp_m = wid & 3;
    const int warp_n = wid >> 2;
    const int g      = lane >> 2;
    const int t      = lane & 3;

    float acc[2][8][4];
    #pragma unroll
    for (int mi = 0; mi < 2; mi++)
        #pragma unroll
        for (int ni = 0; ni < 8; ni++)
            #pragma unroll
            for (int q = 0; q < 4; q++) acc[mi][ni][q] = 0.f;

    gemm_tile((const uint32_t*)sA, (const uint32_t*)sW, acc, warp_m, warp_n, g, t);

    // fused: silu(acc + b3) . W4 -> per-row partials
    float p[2][2] = {{0.f, 0.f}, {0.f, 0.f}};
    #pragma unroll
    for (int ni = 0; ni < 8; ni++) {
        int col = warp_n * 64 + ni * 8 + 2 * t;
        float bb0 = b3[col], bb1 = b3[col + 1];
        float w40 = sW4[col], w41 = sW4[col + 1];
        #pragma unroll
        for (int mi = 0; mi < 2; mi++) {
            p[mi][0] += silu_f(acc[mi][ni][0] + bb0) * w40
                      + silu_f(acc[mi][ni][1] + bb1) * w41;
            p[mi][1] += silu_f(acc[mi][ni][2] + bb0) * w40
                      + silu_f(acc[mi][ni][3] + bb1) * w41;
        }
    }
    #pragma unroll
    for (int mi = 0; mi < 2; mi++)
        #pragma unroll
        for (int h = 0; h < 2; h++) {
            p[mi][h] += __shfl_xor_sync(0xffffffffu, p[mi][h], 1);
            p[mi][h] += __shfl_xor_sync(0xffffffffu, p[mi][h], 2);
        }
    if (t == 0) {
        int base = warp_n * HT + warp_m * 32 + g;
        sPart[base]      = p[0][0];
        sPart[base + 8]  = p[0][1];
        sPart[base + 16] = p[1][0];
        sPart[base + 24] = p[1][1];
    }
    __syncthreads();

    if (tid < HT) {
        int row = tile0 + tid;
        if (row < NUM_GRAPHS)
            out_head[row] = sPart[tid] + sPart[HT + tid] + b4[0];
    }
}

// ---------------------------------------------------------------------------
// launcher
// ---------------------------------------------------------------------------
extern "C" void kernel_launch(void* const* d_in, const int* in_sizes, int n_in,
                              void* d_out, int out_size)
{
    const float* feat  = (const float*)d_in[0];
    const int*   batch = (const int*)d_in[1];   // int32 (JAX x64 disabled)
    const float* W1    = (const float*)d_in[2];
    const float* b1    = (const float*)d_in[3];
    const float* W2    = (const float*)d_in[4];
    const float* b2    = (const float*)d_in[5];
    const float* W3    = (const float*)d_in[6];
    const float* b3    = (const float*)d_in[7];
    const float* W4    = (const float*)d_in[8];
    const float* b4    = (const float*)d_in[9];

    float* out      = (float*)d_out;
    float* out_head = out;                 // [NUM_GRAPHS]
    float* out_feat = nullptr;
    const long long need = (long long)NUM_GRAPHS + (long long)N_ATOMS * DIM;
    if ((long long)out_size >= need)
        out_feat = out + NUM_GRAPHS;       // [N_ATOMS * DIM]

    const int smem_atom = (TILE_M * LDA + DIM * LDA) * 4 + TILE_M * 4;  // ~210.9 KB
    const int smem_head = (2 * HT * LDA + 2 * HT + DIM) * 4;            // ~140.8 KB

    cudaFuncSetAttribute(atom_mlp_pool_kernel,
                         cudaFuncAttributeMaxDynamicSharedMemorySize, smem_atom);
    cudaFuncSetAttribute(graph_head_kernel,
                         cudaFuncAttributeMaxDynamicSharedMemorySize, smem_head);

    zero_pooled_kernel<<<2048, 256>>>();

    int atom_blocks = (N_ATOMS + TILE_M - 1) / TILE_M;       // 3907
    atom_mlp_pool_kernel<<<atom_blocks, NTHREADS, smem_atom>>>(
        feat, batch, W1, b1, W2, b2, out_feat);

    int head_blocks = (NUM_GRAPHS + HT - 1) / HT;            // 782
    graph_head_kernel<<<head_blocks, HNT, smem_head>>>(
        W3, b3, W4, b4, out_head);
}